// round 1
// baseline (speedup 1.0000x reference)
#include <cuda_runtime.h>
#include <cuda_bf16.h>
#include <cstdint>

#define H_  16
#define D_  64
#define DM_ 1024
#define L_  256
#define B_  64
#define M_  (L_*B_)       // 16384 rows (l*B + b)
#define N1_ (H_*4*D_)     // 4096
#define HD_ (H_*D_)       // 1024
#define SCALE_ 0.125f
#define LN_EPS_ 1e-5f

// ---------------- scratch (static device allocations) ----------------
__device__ __nv_bfloat16 g_hb[M_*DM_];        // h in bf16
__device__ __nv_bfloat16 g_wqkv[N1_*DM_];     // qkv_w bf16
__device__ __nv_bfloat16 g_wo[DM_*HD_];       // o_w bf16
__device__ float g_q [B_*H_*L_*D_];           // [B,H,L,D]
__device__ float g_k1[B_*H_*L_*D_];
__device__ float g_k2[B_*H_*L_*D_];
__device__ float g_v [B_*H_*L_*D_];
__device__ __nv_bfloat16 g_lo[M_*HD_];        // gated layer_out, rows l*B+b, cols h*64+d
__device__ float g_attn[M_*DM_];              // attn_out fp32

// ---------------- cast fp32 -> bf16 (vectorized) ----------------
__global__ void cast_kernel(const float* __restrict__ in, __nv_bfloat16* __restrict__ out, int n4) {
    int i = blockIdx.x * blockDim.x + threadIdx.x;
    if (i < n4) {
        float4 f = ((const float4*)in)[i];
        __nv_bfloat162* o = ((__nv_bfloat162*)out) + i*2;
        o[0] = __floats2bfloat162_rn(f.x, f.y);
        o[1] = __floats2bfloat162_rn(f.z, f.w);
    }
}

// ---------------- bf16 NT GEMM: C[M,N] = A[M,K] * B[N,K]^T ----------------
__device__ __forceinline__ void mma_bf16(float& d0, float& d1, float& d2, float& d3,
                                         uint32_t a0, uint32_t a1, uint32_t a2, uint32_t a3,
                                         uint32_t b0, uint32_t b1) {
    asm volatile(
        "mma.sync.aligned.m16n8k16.row.col.f32.bf16.bf16.f32 "
        "{%0,%1,%2,%3},{%4,%5,%6,%7},{%8,%9},{%0,%1,%2,%3};\n"
        : "+f"(d0), "+f"(d1), "+f"(d2), "+f"(d3)
        : "r"(a0), "r"(a1), "r"(a2), "r"(a3), "r"(b0), "r"(b1));
}

#define SST 40   // smem row stride in bf16 (80B: conflict-free frag loads, 16B-aligned stores)

// EPI=0: scatter to q/k1/k2/v in [B,H,L,D]; EPI=1: plain row-major C=o0
template<int EPI>
__global__ void __launch_bounds__(256) gemm_nt(
    const __nv_bfloat16* __restrict__ A, const __nv_bfloat16* __restrict__ Bw,
    int M, int N, int K,
    float* __restrict__ o0, float* __restrict__ o1,
    float* __restrict__ o2, float* __restrict__ o3)
{
    __shared__ __align__(16) __nv_bfloat16 As[128*SST];
    __shared__ __align__(16) __nv_bfloat16 Bs[128*SST];

    const int tid = threadIdx.x, lane = tid & 31, w = tid >> 5;
    const int wm = w & 3, wn = w >> 2;              // warp grid 4(m) x 2(n)
    const int m0 = blockIdx.y * 128, n0 = blockIdx.x * 128;
    const int lr = tid >> 2, lc = tid & 3;          // load row / 16B chunk

    const __nv_bfloat16* Ag = A + (size_t)(m0 + lr) * K + lc * 8;
    const __nv_bfloat16* Bg = Bw + (size_t)(n0 + lr) * K + lc * 8;

    float acc[2][8][4];
    #pragma unroll
    for (int i = 0; i < 2; i++)
        #pragma unroll
        for (int j = 0; j < 8; j++)
            #pragma unroll
            for (int k = 0; k < 4; k++) acc[i][j][k] = 0.f;

    const int nk = K / 32;
    for (int kb = 0; kb < nk; kb++) {
        uint4 av0 = *(const uint4*)(Ag + kb * 32);
        uint4 av1 = *(const uint4*)(Ag + (size_t)64 * K + kb * 32);
        uint4 bv0 = *(const uint4*)(Bg + kb * 32);
        uint4 bv1 = *(const uint4*)(Bg + (size_t)64 * K + kb * 32);
        __syncthreads();
        *(uint4*)&As[lr * SST + lc * 8]        = av0;
        *(uint4*)&As[(lr + 64) * SST + lc * 8] = av1;
        *(uint4*)&Bs[lr * SST + lc * 8]        = bv0;
        *(uint4*)&Bs[(lr + 64) * SST + lc * 8] = bv1;
        __syncthreads();

        #pragma unroll
        for (int kk = 0; kk < 32; kk += 16) {
            uint32_t af[2][4], bfr[8][2];
            #pragma unroll
            for (int mt = 0; mt < 2; mt++) {
                int ar = wm * 32 + mt * 16 + (lane >> 2);
                const __nv_bfloat16* p = &As[ar * SST + kk + (lane & 3) * 2];
                af[mt][0] = *(const uint32_t*)p;
                af[mt][1] = *(const uint32_t*)(p + 8 * SST);
                af[mt][2] = *(const uint32_t*)(p + 8);
                af[mt][3] = *(const uint32_t*)(p + 8 * SST + 8);
            }
            #pragma unroll
            for (int nt = 0; nt < 8; nt++) {
                int br = wn * 64 + nt * 8 + (lane >> 2);
                const __nv_bfloat16* p = &Bs[br * SST + kk + (lane & 3) * 2];
                bfr[nt][0] = *(const uint32_t*)p;
                bfr[nt][1] = *(const uint32_t*)(p + 8);
            }
            #pragma unroll
            for (int mt = 0; mt < 2; mt++)
                #pragma unroll
                for (int nt = 0; nt < 8; nt++)
                    mma_bf16(acc[mt][nt][0], acc[mt][nt][1], acc[mt][nt][2], acc[mt][nt][3],
                             af[mt][0], af[mt][1], af[mt][2], af[mt][3],
                             bfr[nt][0], bfr[nt][1]);
        }
    }

    // epilogue
    #pragma unroll
    for (int mt = 0; mt < 2; mt++) {
        #pragma unroll
        for (int nt = 0; nt < 8; nt++) {
            int r0 = m0 + wm * 32 + mt * 16 + (lane >> 2);
            int c0 = n0 + wn * 64 + nt * 8 + (lane & 3) * 2;
            if (EPI == 0) {
                int head = c0 >> 8;
                int part = (c0 >> 6) & 3;
                int d    = c0 & 63;
                float* bp = (part == 0) ? o0 : (part == 1) ? o1 : (part == 2) ? o2 : o3;
                #pragma unroll
                for (int rr = 0; rr < 2; rr++) {
                    int m = r0 + rr * 8;
                    int l = m >> 6, b = m & 63;
                    size_t off = (((size_t)(b * H_ + head) * L_ + l) * D_ + d);
                    float2 v = make_float2(acc[mt][nt][rr * 2], acc[mt][nt][rr * 2 + 1]);
                    *(float2*)(bp + off) = v;
                }
            } else {
                #pragma unroll
                for (int rr = 0; rr < 2; rr++) {
                    int m = r0 + rr * 8;
                    float2 v = make_float2(acc[mt][nt][rr * 2], acc[mt][nt][rr * 2 + 1]);
                    *(float2*)(o0 + (size_t)m * N + c0) = v;
                }
            }
        }
    }
}

// ---------------- phi: e = elu(x)+1, normalize over D=64 (in place) ----------------
__global__ void __launch_bounds__(256) phi_kernel(float* q, float* k1, float* k2) {
    float* buf = (blockIdx.y == 0) ? q : (blockIdx.y == 1) ? k1 : k2;
    int row  = blockIdx.x * 8 + (threadIdx.x >> 5);
    int lane = threadIdx.x & 31;
    float* r = buf + (size_t)row * 64;
    float x0 = r[lane], x1 = r[lane + 32];
    float e0 = (x0 > 0.f) ? (x0 + 1.f) : expf(x0);
    float e1 = (x1 > 0.f) ? (x1 + 1.f) : expf(x1);
    float s = e0 + e1;
    #pragma unroll
    for (int o = 16; o > 0; o >>= 1) s += __shfl_xor_sync(0xFFFFFFFFu, s, o);
    float inv = 1.f / s;
    r[lane]      = e0 * inv;
    r[lane + 32] = e1 * inv;
}

// ---------------- fused two-memory fast-weight + gating ----------------
// One CTA per (b,h). 4 chunks of 64. 16x16 threads, each owns 4x4 sub-tiles.
#define FWP 65
#define FW_SMEM (8 * 64 * FWP * 4)

__global__ void __launch_bounds__(256) fw_kernel(const float* __restrict__ pi0,
                                                 __nv_bfloat16* __restrict__ lo)
{
    extern __shared__ float sm[];
    float* qs  = sm;
    float* k1s = qs  + 64 * FWP;
    float* k2s = k1s + 64 * FWP;
    float* vs  = k2s + 64 * FWP;
    float* s1s = vs  + 64 * FWP;
    float* s2s = s1s + 64 * FWP;
    float* W1  = s2s + 64 * FWP;
    float* W2  = W1  + 64 * FWP;

    const int bh = blockIdx.x;
    const int b = bh >> 4, h = bh & 15;
    const int tid = threadIdx.x;
    const int ty = tid >> 4, tx = tid & 15;
    const size_t base = (size_t)bh * (L_ * D_);

    const float* qg  = g_q  + base;
    const float* k1g = g_k1 + base;
    const float* k2g = g_k2 + base;
    const float* vg  = g_v  + base;

    // zero states
    #pragma unroll
    for (int i = 0; i < 4; i++)
        #pragma unroll
        for (int j = 0; j < 4; j++) {
            W1[(4 * ty + i) * FWP + 4 * tx + j] = 0.f;
            W2[(4 * ty + i) * FWP + 4 * tx + j] = 0.f;
        }

    for (int c = 0; c < 4; c++) {
        // ---- load q,k1,k2,v chunk tiles [64,64] ----
        const float* srcs[4] = { qg + c * 4096, k1g + c * 4096, k2g + c * 4096, vg + c * 4096 };
        float* dsts[4] = { qs, k1s, k2s, vs };
        __syncthreads();   // protect k1s/vs reads from previous chunk's W-update
        #pragma unroll
        for (int t4 = 0; t4 < 4; t4++) {
            const float* gp = srcs[t4];
            float* dp = dsts[t4];
            #pragma unroll
            for (int i = 0; i < 4; i++) {
                int idx = tid + i * 256;
                int t = idx >> 4, c4 = idx & 15;
                float4 v = *(const float4*)(gp + t * 64 + c4 * 4);
                float* d = dp + t * FWP + c4 * 4;
                d[0] = v.x; d[1] = v.y; d[2] = v.z; d[3] = v.w;
            }
        }
        __syncthreads();

        // ---- masked scores: s[t][s] = (q_t . k_s) * (s<=t) ----
        float a1[4][4], a2[4][4];
        #pragma unroll
        for (int i = 0; i < 4; i++)
            #pragma unroll
            for (int j = 0; j < 4; j++) { a1[i][j] = 0.f; a2[i][j] = 0.f; }
        for (int d0 = 0; d0 < 64; d0++) {
            float qv[4], kv1[4], kv2[4];
            #pragma unroll
            for (int i = 0; i < 4; i++) qv[i]  = qs [(4 * ty + i) * FWP + d0];
            #pragma unroll
            for (int j = 0; j < 4; j++) { kv1[j] = k1s[(4 * tx + j) * FWP + d0];
                                          kv2[j] = k2s[(4 * tx + j) * FWP + d0]; }
            #pragma unroll
            for (int i = 0; i < 4; i++)
                #pragma unroll
                for (int j = 0; j < 4; j++) {
                    a1[i][j] += qv[i] * kv1[j];
                    a2[i][j] += qv[i] * kv2[j];
                }
        }
        #pragma unroll
        for (int i = 0; i < 4; i++)
            #pragma unroll
            for (int j = 0; j < 4; j++) {
                int t = 4 * ty + i, s = 4 * tx + j;
                s1s[t * FWP + s] = (s <= t) ? a1[i][j] : 0.f;
                s2s[t * FWP + s] = (s <= t) ? a2[i][j] : 0.f;
            }
        __syncthreads();

        // ---- out = scores @ v + q @ W ----
        float o1[4][4], o2[4][4];
        #pragma unroll
        for (int i = 0; i < 4; i++)
            #pragma unroll
            for (int j = 0; j < 4; j++) { o1[i][j] = 0.f; o2[i][j] = 0.f; }
        for (int s = 0; s < 64; s++) {
            float vv[4], x1[4], x2[4];
            #pragma unroll
            for (int j = 0; j < 4; j++) vv[j] = vs[s * FWP + 4 * tx + j];
            #pragma unroll
            for (int i = 0; i < 4; i++) { x1[i] = s1s[(4 * ty + i) * FWP + s];
                                          x2[i] = s2s[(4 * ty + i) * FWP + s]; }
            #pragma unroll
            for (int i = 0; i < 4; i++)
                #pragma unroll
                for (int j = 0; j < 4; j++) {
                    o1[i][j] += x1[i] * vv[j];
                    o2[i][j] += x2[i] * vv[j];
                }
        }
        for (int e = 0; e < 64; e++) {
            float w1v[4], w2v[4], qv[4];
            #pragma unroll
            for (int j = 0; j < 4; j++) { w1v[j] = W1[e * FWP + 4 * tx + j];
                                          w2v[j] = W2[e * FWP + 4 * tx + j]; }
            #pragma unroll
            for (int i = 0; i < 4; i++) qv[i] = qs[(4 * ty + i) * FWP + e];
            #pragma unroll
            for (int i = 0; i < 4; i++)
                #pragma unroll
                for (int j = 0; j < 4; j++) {
                    o1[i][j] += qv[i] * w1v[j];
                    o2[i][j] += qv[i] * w2v[j];
                }
        }

        // ---- gate with pi0, scale, write bf16 layer_out [l*B+b, h*64+d] ----
        #pragma unroll
        for (int i = 0; i < 4; i++) {
            int t = 4 * ty + i, l = c * 64 + t;
            float p = pi0[h * 256 + l];
            p = fminf(fmaxf(p, 0.f), 1.f);
            size_t ro = ((size_t)(l * B_ + b)) * HD_ + h * 64;
            #pragma unroll
            for (int j = 0; j < 4; j++) {
                int dd = 4 * tx + j;
                float val = SCALE_ * (o1[i][j] * p + o2[i][j] * (1.f - p));
                lo[ro + dd] = __float2bfloat16(val);
            }
        }
        __syncthreads();   // out-phase reads of W done before update writes

        // ---- W += k^T @ v ----
        float u1[4][4], u2[4][4];
        #pragma unroll
        for (int i = 0; i < 4; i++)
            #pragma unroll
            for (int j = 0; j < 4; j++) { u1[i][j] = 0.f; u2[i][j] = 0.f; }
        for (int s = 0; s < 64; s++) {
            float kv1[4], kv2[4], vv[4];
            #pragma unroll
            for (int i = 0; i < 4; i++) { kv1[i] = k1s[s * FWP + 4 * ty + i];
                                          kv2[i] = k2s[s * FWP + 4 * ty + i]; }
            #pragma unroll
            for (int j = 0; j < 4; j++) vv[j] = vs[s * FWP + 4 * tx + j];
            #pragma unroll
            for (int i = 0; i < 4; i++)
                #pragma unroll
                for (int j = 0; j < 4; j++) {
                    u1[i][j] += kv1[i] * vv[j];
                    u2[i][j] += kv2[i] * vv[j];
                }
        }
        #pragma unroll
        for (int i = 0; i < 4; i++)
            #pragma unroll
            for (int j = 0; j < 4; j++) {
                W1[(4 * ty + i) * FWP + 4 * tx + j] += u1[i][j];
                W2[(4 * ty + i) * FWP + 4 * tx + j] += u2[i][j];
            }
    }
}

// ---------------- residual + LayerNorm ----------------
__global__ void __launch_bounds__(256) ln_kernel(const float* __restrict__ hin,
                                                 const float* __restrict__ attn,
                                                 const float* __restrict__ gamma,
                                                 const float* __restrict__ beta,
                                                 float* __restrict__ out)
{
    int row = blockIdx.x;
    int tid = threadIdx.x;
    const float4* hr = (const float4*)(hin  + (size_t)row * DM_);
    const float4* ar = (const float4*)(attn + (size_t)row * DM_);
    float4 hv = hr[tid], av = ar[tid];
    float x0 = hv.x + av.x, x1 = hv.y + av.y, x2 = hv.z + av.z, x3 = hv.w + av.w;
    float s  = x0 + x1 + x2 + x3;
    float sq = x0 * x0 + x1 * x1 + x2 * x2 + x3 * x3;
    int lane = tid & 31, w = tid >> 5;
    #pragma unroll
    for (int o = 16; o > 0; o >>= 1) {
        s  += __shfl_xor_sync(0xFFFFFFFFu, s,  o);
        sq += __shfl_xor_sync(0xFFFFFFFFu, sq, o);
    }
    __shared__ float rs[8], rq[8];
    if (lane == 0) { rs[w] = s; rq[w] = sq; }
    __syncthreads();
    float ts = 0.f, tq = 0.f;
    #pragma unroll
    for (int i = 0; i < 8; i++) { ts += rs[i]; tq += rq[i]; }
    float mu  = ts * (1.f / DM_);
    float var = tq * (1.f / DM_) - mu * mu;
    float inv = rsqrtf(var + LN_EPS_);

    const float4 g4 = ((const float4*)gamma)[tid];
    const float4 b4 = ((const float4*)beta)[tid];
    float4 o4;
    o4.x = (x0 - mu) * inv * g4.x + b4.x;
    o4.y = (x1 - mu) * inv * g4.y + b4.y;
    o4.z = (x2 - mu) * inv * g4.z + b4.z;
    o4.w = (x3 - mu) * inv * g4.w + b4.w;
    ((float4*)(out + (size_t)row * DM_))[tid] = o4;
}

// ---------------- launch ----------------
extern "C" void kernel_launch(void* const* d_in, const int* in_sizes, int n_in,
                              void* d_out, int out_size) {
    (void)in_sizes; (void)n_in; (void)out_size;
    const float* h      = (const float*)d_in[0];
    const float* qkv_w  = (const float*)d_in[1];
    const float* o_w    = (const float*)d_in[2];
    const float* gamma  = (const float*)d_in[3];
    const float* beta   = (const float*)d_in[4];
    const float* pi0    = (const float*)d_in[5];
    float* out = (float*)d_out;

    __nv_bfloat16 *hb, *wqkv, *wo, *lo;
    float *qb, *k1b, *k2b, *vb, *attn;
    cudaGetSymbolAddress((void**)&hb,   g_hb);
    cudaGetSymbolAddress((void**)&wqkv, g_wqkv);
    cudaGetSymbolAddress((void**)&wo,   g_wo);
    cudaGetSymbolAddress((void**)&qb,   g_q);
    cudaGetSymbolAddress((void**)&k1b,  g_k1);
    cudaGetSymbolAddress((void**)&k2b,  g_k2);
    cudaGetSymbolAddress((void**)&vb,   g_v);
    cudaGetSymbolAddress((void**)&lo,   g_lo);
    cudaGetSymbolAddress((void**)&attn, g_attn);

    // casts
    cast_kernel<<<(M_*DM_/4 + 255) / 256, 256>>>(h, hb, M_*DM_/4);
    cast_kernel<<<(N1_*DM_/4 + 255) / 256, 256>>>(qkv_w, wqkv, N1_*DM_/4);
    cast_kernel<<<(DM_*HD_/4 + 255) / 256, 256>>>(o_w, wo, DM_*HD_/4);

    // QKV GEMM with scatter epilogue
    gemm_nt<0><<<dim3(N1_/128, M_/128), 256>>>(hb, wqkv, M_, N1_, DM_, qb, k1b, k2b, vb);

    // phi on q, k1, k2
    phi_kernel<<<dim3((B_*H_*L_)/8, 3), 256>>>(qb, k1b, k2b);

    // fast-weight + gate
    cudaFuncSetAttribute(fw_kernel, cudaFuncAttributeMaxDynamicSharedMemorySize, FW_SMEM);
    fw_kernel<<<B_*H_, 256, FW_SMEM>>>(pi0, lo);

    // output projection
    gemm_nt<1><<<dim3(DM_/128, M_/128), 256>>>(lo, wo, M_, DM_, HD_, attn, nullptr, nullptr, nullptr);

    // residual + LN
    ln_kernel<<<M_, 256>>>(h, attn, gamma, beta, out);
}

// round 2
// speedup vs baseline: 1.2834x; 1.2834x over previous
#include <cuda_runtime.h>
#include <cuda_bf16.h>
#include <cstdint>

#define H_  16
#define D_  64
#define DM_ 1024
#define L_  256
#define B_  64
#define M_  (L_*B_)       // 16384 rows (l*B + b)
#define N1_ (H_*4*D_)     // 4096
#define HD_ (H_*D_)       // 1024
#define SCALE_ 0.125f
#define LN_EPS_ 1e-5f

// ---------------- scratch (static device allocations) ----------------
__device__ __nv_bfloat16 g_hb[M_*DM_];        // h in bf16
__device__ __nv_bfloat16 g_wqkv[N1_*DM_];     // qkv_w bf16
__device__ __nv_bfloat16 g_wo[DM_*HD_];       // o_w bf16
__device__ float g_q [B_*H_*L_*D_];           // [B,H,L,D] pre-phi
__device__ float g_k1[B_*H_*L_*D_];
__device__ float g_k2[B_*H_*L_*D_];
__device__ float g_v [B_*H_*L_*D_];
__device__ __nv_bfloat16 g_lo[M_*HD_];        // gated layer_out, rows l*B+b, cols h*64+d
__device__ float g_attn[M_*DM_];              // attn_out fp32

// ---------------- helpers ----------------
__global__ void cast_kernel(const float* __restrict__ in, __nv_bfloat16* __restrict__ out, int n4) {
    int i = blockIdx.x * blockDim.x + threadIdx.x;
    if (i < n4) {
        float4 f = ((const float4*)in)[i];
        __nv_bfloat162* o = ((__nv_bfloat162*)out) + i*2;
        o[0] = __floats2bfloat162_rn(f.x, f.y);
        o[1] = __floats2bfloat162_rn(f.z, f.w);
    }
}

__device__ __forceinline__ void mma_bf16(float& d0, float& d1, float& d2, float& d3,
                                         uint32_t a0, uint32_t a1, uint32_t a2, uint32_t a3,
                                         uint32_t b0, uint32_t b1) {
    asm volatile(
        "mma.sync.aligned.m16n8k16.row.col.f32.bf16.bf16.f32 "
        "{%0,%1,%2,%3},{%4,%5,%6,%7},{%8,%9},{%0,%1,%2,%3};\n"
        : "+f"(d0), "+f"(d1), "+f"(d2), "+f"(d3)
        : "r"(a0), "r"(a1), "r"(a2), "r"(a3), "r"(b0), "r"(b1));
}

__device__ __forceinline__ void ldsm4(uint32_t a, uint32_t& r0, uint32_t& r1, uint32_t& r2, uint32_t& r3) {
    asm volatile("ldmatrix.sync.aligned.m8n8.x4.shared.b16 {%0,%1,%2,%3},[%4];"
                 : "=r"(r0), "=r"(r1), "=r"(r2), "=r"(r3) : "r"(a));
}
__device__ __forceinline__ void ldsm4t(uint32_t a, uint32_t& r0, uint32_t& r1, uint32_t& r2, uint32_t& r3) {
    asm volatile("ldmatrix.sync.aligned.m8n8.x4.trans.shared.b16 {%0,%1,%2,%3},[%4];"
                 : "=r"(r0), "=r"(r1), "=r"(r2), "=r"(r3) : "r"(a));
}

#define CP_ASYNC16(dst, src) asm volatile("cp.async.cg.shared.global [%0], [%1], 16;" :: "r"(dst), "l"(src))
#define CP_COMMIT() asm volatile("cp.async.commit_group;")
#define CP_WAIT(n)  asm volatile("cp.async.wait_group %0;" :: "n"(n))

// ---------------- bf16 NT GEMM: C[M,N] = A[M,K] * B[N,K]^T ----------------
// 128x128x64 tiles, ldmatrix fragments, 2-stage cp.async pipeline.
// smem layout: rows of 64 bf16 (128B), 16B chunk cc stored at (cc ^ (r&7)).
#define GEMM_SMEM (4 * 128 * 64 * 2)   // A0,A1,B0,B1 = 64KB

template<int EPI>
__global__ void __launch_bounds__(256) gemm_nt(
    const __nv_bfloat16* __restrict__ A, const __nv_bfloat16* __restrict__ Bw,
    int M, int N, int K,
    float* __restrict__ o0, float* __restrict__ o1,
    float* __restrict__ o2, float* __restrict__ o3)
{
    extern __shared__ __nv_bfloat16 gsm[];
    const uint32_t sA = (uint32_t)__cvta_generic_to_shared(gsm);            // A: 2 stages x 16KB
    const uint32_t sB = sA + 32768;                                         // B: 2 stages x 16KB

    const int tid = threadIdx.x, lane = tid & 31, w = tid >> 5;
    const int wm = w & 3, wn = w >> 2;                 // warp grid 4(m) x 2(n)
    const int m0 = blockIdx.y * 128, n0 = blockIdx.x * 128;

    // loader: 256 threads cover 32 rows x 8 chunks per pass; 4 passes
    const int lr = tid >> 3, lcc = tid & 7;
    const __nv_bfloat16* Ag = A + (size_t)(m0 + lr) * K + lcc * 8;
    const __nv_bfloat16* Bg = Bw + (size_t)(n0 + lr) * K + lcc * 8;
    uint32_t stoff[4];
    #pragma unroll
    for (int g = 0; g < 4; g++) {
        int r = lr + 32 * g;
        stoff[g] = r * 128 + ((lcc ^ (r & 7)) * 16);
    }

    // ldmatrix address components
    const int aRow = wm * 32 + ((lane >> 3) & 1) * 8 + (lane & 7);  // + mt*16
    const int aCk  = (lane >> 4);                                   // + kk8
    const int bRow = wn * 64 + (lane >> 4) * 8 + (lane & 7);        // + np*16
    const int bCk  = ((lane >> 3) & 1);                             // + kk8

    float acc[2][8][4];
    #pragma unroll
    for (int i = 0; i < 2; i++)
        #pragma unroll
        for (int j = 0; j < 8; j++)
            #pragma unroll
            for (int k = 0; k < 4; k++) acc[i][j][k] = 0.f;

    const int nk = K >> 6;

    // prologue: stage 0
    #pragma unroll
    for (int g = 0; g < 4; g++) {
        CP_ASYNC16(sA + stoff[g], Ag + (size_t)(32 * g) * K);
        CP_ASYNC16(sB + stoff[g], Bg + (size_t)(32 * g) * K);
    }
    CP_COMMIT();

    for (int kb = 0; kb < nk; kb++) {
        const int cur = kb & 1;
        if (kb + 1 < nk) {
            const int nxt = (kb + 1) & 1;
            #pragma unroll
            for (int g = 0; g < 4; g++) {
                CP_ASYNC16(sA + nxt * 16384 + stoff[g], Ag + (size_t)(32 * g) * K + (kb + 1) * 64);
                CP_ASYNC16(sB + nxt * 16384 + stoff[g], Bg + (size_t)(32 * g) * K + (kb + 1) * 64);
            }
        }
        CP_COMMIT();
        CP_WAIT(1);
        __syncthreads();

        const uint32_t ab = sA + cur * 16384;
        const uint32_t bb = sB + cur * 16384;
        #pragma unroll
        for (int kk8 = 0; kk8 < 8; kk8 += 2) {
            uint32_t af[2][4], bfr[4][4];
            #pragma unroll
            for (int mt = 0; mt < 2; mt++) {
                int r = aRow + mt * 16, ck = kk8 + aCk;
                ldsm4(ab + r * 128 + ((ck ^ (r & 7)) * 16), af[mt][0], af[mt][1], af[mt][2], af[mt][3]);
            }
            #pragma unroll
            for (int np = 0; np < 4; np++) {
                int r = bRow + np * 16, ck = kk8 + bCk;
                ldsm4(bb + r * 128 + ((ck ^ (r & 7)) * 16), bfr[np][0], bfr[np][1], bfr[np][2], bfr[np][3]);
            }
            #pragma unroll
            for (int mt = 0; mt < 2; mt++)
                #pragma unroll
                for (int np = 0; np < 4; np++) {
                    mma_bf16(acc[mt][2*np][0], acc[mt][2*np][1], acc[mt][2*np][2], acc[mt][2*np][3],
                             af[mt][0], af[mt][1], af[mt][2], af[mt][3], bfr[np][0], bfr[np][1]);
                    mma_bf16(acc[mt][2*np+1][0], acc[mt][2*np+1][1], acc[mt][2*np+1][2], acc[mt][2*np+1][3],
                             af[mt][0], af[mt][1], af[mt][2], af[mt][3], bfr[np][2], bfr[np][3]);
                }
        }
        __syncthreads();
    }

    // epilogue
    #pragma unroll
    for (int mt = 0; mt < 2; mt++) {
        #pragma unroll
        for (int nt = 0; nt < 8; nt++) {
            int r0 = m0 + wm * 32 + mt * 16 + (lane >> 2);
            int c0 = n0 + wn * 64 + nt * 8 + (lane & 3) * 2;
            if (EPI == 0) {
                int head = c0 >> 8;
                int part = (c0 >> 6) & 3;
                int d    = c0 & 63;
                float* bp = (part == 0) ? o0 : (part == 1) ? o1 : (part == 2) ? o2 : o3;
                #pragma unroll
                for (int rr = 0; rr < 2; rr++) {
                    int m = r0 + rr * 8;
                    int l = m >> 6, b = m & 63;
                    size_t off = (((size_t)(b * H_ + head) * L_ + l) * D_ + d);
                    float2 v = make_float2(acc[mt][nt][rr * 2], acc[mt][nt][rr * 2 + 1]);
                    *(float2*)(bp + off) = v;
                }
            } else {
                #pragma unroll
                for (int rr = 0; rr < 2; rr++) {
                    int m = r0 + rr * 8;
                    float2 v = make_float2(acc[mt][nt][rr * 2], acc[mt][nt][rr * 2 + 1]);
                    *(float2*)(o0 + (size_t)m * N + c0) = v;
                }
            }
        }
    }
}

// ---------------- fused phi + two-memory fast-weight + gating (tensor cores) ----------------
// One CTA per (b,h), 128 threads (4 warps), warp w owns 16-row strip.
// smem tiles (64x64 bf16, swizzled 128B rows): 0=Q 1=K1 2=K2 3=V 4=S1 5=S2 6=W1bf 7=W2bf
#define FW_SMEM (8 * 4096 * 2)   // 64KB

__device__ __forceinline__ int offe(int t, int r, int c) {
    return t * 4096 + r * 64 + ((((c >> 3) ^ (r & 7))) << 3) + (c & 7);
}

__global__ void __launch_bounds__(128) fw_kernel(const float* __restrict__ pi0,
                                                 __nv_bfloat16* __restrict__ lo)
{
    extern __shared__ __nv_bfloat16 fs[];
    const uint32_t sb = (uint32_t)__cvta_generic_to_shared(fs);
    const int bh = blockIdx.x, b = bh >> 4, h = bh & 15;
    const int tid = threadIdx.x, lane = tid & 31, w = tid >> 5;
    const size_t base = (size_t)bh * (L_ * D_);
    const float* qg  = g_q  + base;
    const float* k1g = g_k1 + base;
    const float* k2g = g_k2 + base;
    const float* vg  = g_v  + base;

    float W1a[8][4], W2a[8][4];
    #pragma unroll
    for (int n = 0; n < 8; n++)
        #pragma unroll
        for (int q = 0; q < 4; q++) { W1a[n][q] = 0.f; W2a[n][q] = 0.f; }

    // fragment address components
    const int arow = 16 * w + ((lane >> 3) & 1) * 8 + (lane & 7); // A / S ldsm rows (own strip)
    const int ac0  = (lane >> 4);
    const int brow = (lane >> 4) * 8 + (lane & 7);                // B non-trans rows (+16*np)
    const int bck  = ((lane >> 3) & 1);
    const int trow = ((lane >> 3) & 1) * 8 + (lane & 7);          // B trans rows (+16*ks)
    const int tck  = (lane >> 4);                                 // B trans chunk (+2*np)
    const int karow = (lane >> 4) * 8 + (lane & 7);               // A trans (K^T) rows (+16*ks)
    const int kack  = ((lane >> 3) & 1);                          // chunk (+2*w)

    const int tlo = 16 * w + (lane >> 2);
    const int cc0 = (lane & 3) * 2;

    for (int c = 0; c < 4; c++) {
        __syncthreads();   // previous chunk fully done before overwriting smem

        // ---- load + phi (q,k1,k2) and load (v) ----
        #pragma unroll
        for (int m = 0; m < 3; m++) {
            const float* sp = ((m == 0) ? qg : (m == 1) ? k1g : k2g) + c * 4096;
            for (int rr = 0; rr < 16; rr++) {
                int r = 16 * w + rr;
                float2 xv = *(const float2*)(sp + r * 64 + 2 * lane);
                float e0 = (xv.x > 0.f) ? (xv.x + 1.f) : expf(xv.x);
                float e1 = (xv.y > 0.f) ? (xv.y + 1.f) : expf(xv.y);
                float s = e0 + e1;
                #pragma unroll
                for (int o = 16; o > 0; o >>= 1) s += __shfl_xor_sync(0xFFFFFFFFu, s, o);
                float inv = 1.f / s;
                *(__nv_bfloat162*)&fs[offe(m, r, 2 * lane)] = __floats2bfloat162_rn(e0 * inv, e1 * inv);
            }
        }
        for (int rr = 0; rr < 16; rr++) {
            int r = 16 * w + rr;
            float2 xv = *(const float2*)(vg + c * 4096 + r * 64 + 2 * lane);
            *(__nv_bfloat162*)&fs[offe(3, r, 2 * lane)] = __floats2bfloat162_rn(xv.x, xv.y);
        }

        // ---- stage W (fp32 acc -> bf16 smem) for the q@W term ----
        if (c) {
            #pragma unroll
            for (int n = 0; n < 8; n++) {
                #pragma unroll
                for (int hf = 0; hf < 2; hf++) {
                    int r = 16 * w + (lane >> 2) + 8 * hf;
                    int cc = 8 * n + cc0;
                    *(__nv_bfloat162*)&fs[offe(6, r, cc)] = __floats2bfloat162_rn(W1a[n][2*hf], W1a[n][2*hf+1]);
                    *(__nv_bfloat162*)&fs[offe(7, r, cc)] = __floats2bfloat162_rn(W2a[n][2*hf], W2a[n][2*hf+1]);
                }
            }
        }
        __syncthreads();

        // ---- Q A-fragments (held for S and q@W) ----
        uint32_t QA[4][4];
        #pragma unroll
        for (int ks = 0; ks < 4; ks++)
            ldsm4(sb + 2 * offe(0, arow, (2 * ks + ac0) * 8), QA[ks][0], QA[ks][1], QA[ks][2], QA[ks][3]);

        float O1[8][4], O2[8][4];
        #pragma unroll
        for (int n = 0; n < 8; n++)
            #pragma unroll
            for (int q = 0; q < 4; q++) { O1[n][q] = 0.f; O2[n][q] = 0.f; }

        // ---- S1 = Q K1^T, S2 = Q K2^T ----
        #pragma unroll
        for (int ks = 0; ks < 4; ks++)
            #pragma unroll
            for (int np = 0; np < 4; np++) {
                uint32_t b0, b1, b2, b3;
                ldsm4(sb + 2 * offe(1, 16 * np + brow, (2 * ks + bck) * 8), b0, b1, b2, b3);
                mma_bf16(O1[2*np][0], O1[2*np][1], O1[2*np][2], O1[2*np][3],
                         QA[ks][0], QA[ks][1], QA[ks][2], QA[ks][3], b0, b1);
                mma_bf16(O1[2*np+1][0], O1[2*np+1][1], O1[2*np+1][2], O1[2*np+1][3],
                         QA[ks][0], QA[ks][1], QA[ks][2], QA[ks][3], b2, b3);
                ldsm4(sb + 2 * offe(2, 16 * np + brow, (2 * ks + bck) * 8), b0, b1, b2, b3);
                mma_bf16(O2[2*np][0], O2[2*np][1], O2[2*np][2], O2[2*np][3],
                         QA[ks][0], QA[ks][1], QA[ks][2], QA[ks][3], b0, b1);
                mma_bf16(O2[2*np+1][0], O2[2*np+1][1], O2[2*np+1][2], O2[2*np+1][3],
                         QA[ks][0], QA[ks][1], QA[ks][2], QA[ks][3], b2, b3);
            }

        // ---- mask (s<=t) + store S bf16, reset acc ----
        #pragma unroll
        for (int nt = 0; nt < 8; nt++) {
            int s0 = 8 * nt + cc0;
            float v0 = (s0     <= tlo) ? O1[nt][0] : 0.f;
            float v1 = (s0 + 1 <= tlo) ? O1[nt][1] : 0.f;
            float v2 = (s0     <= tlo + 8) ? O1[nt][2] : 0.f;
            float v3 = (s0 + 1 <= tlo + 8) ? O1[nt][3] : 0.f;
            *(__nv_bfloat162*)&fs[offe(4, tlo, s0)]     = __floats2bfloat162_rn(v0, v1);
            *(__nv_bfloat162*)&fs[offe(4, tlo + 8, s0)] = __floats2bfloat162_rn(v2, v3);
            v0 = (s0     <= tlo) ? O2[nt][0] : 0.f;
            v1 = (s0 + 1 <= tlo) ? O2[nt][1] : 0.f;
            v2 = (s0     <= tlo + 8) ? O2[nt][2] : 0.f;
            v3 = (s0 + 1 <= tlo + 8) ? O2[nt][3] : 0.f;
            *(__nv_bfloat162*)&fs[offe(5, tlo, s0)]     = __floats2bfloat162_rn(v0, v1);
            *(__nv_bfloat162*)&fs[offe(5, tlo + 8, s0)] = __floats2bfloat162_rn(v2, v3);
            #pragma unroll
            for (int q = 0; q < 4; q++) { O1[nt][q] = 0.f; O2[nt][q] = 0.f; }
        }
        __syncwarp();

        // ---- O = S@V (+ Q@W) ----
        #pragma unroll
        for (int ks = 0; ks < 4; ks++) {
            uint32_t SA1[4], SA2[4];
            ldsm4(sb + 2 * offe(4, arow, (2 * ks + ac0) * 8), SA1[0], SA1[1], SA1[2], SA1[3]);
            ldsm4(sb + 2 * offe(5, arow, (2 * ks + ac0) * 8), SA2[0], SA2[1], SA2[2], SA2[3]);
            #pragma unroll
            for (int np = 0; np < 4; np++) {
                uint32_t vb0, vb1, vb2, vb3;
                ldsm4t(sb + 2 * offe(3, 16 * ks + trow, (2 * np + tck) * 8), vb0, vb1, vb2, vb3);
                mma_bf16(O1[2*np][0], O1[2*np][1], O1[2*np][2], O1[2*np][3],
                         SA1[0], SA1[1], SA1[2], SA1[3], vb0, vb1);
                mma_bf16(O1[2*np+1][0], O1[2*np+1][1], O1[2*np+1][2], O1[2*np+1][3],
                         SA1[0], SA1[1], SA1[2], SA1[3], vb2, vb3);
                mma_bf16(O2[2*np][0], O2[2*np][1], O2[2*np][2], O2[2*np][3],
                         SA2[0], SA2[1], SA2[2], SA2[3], vb0, vb1);
                mma_bf16(O2[2*np+1][0], O2[2*np+1][1], O2[2*np+1][2], O2[2*np+1][3],
                         SA2[0], SA2[1], SA2[2], SA2[3], vb2, vb3);
                if (c) {
                    uint32_t wb0, wb1, wb2, wb3;
                    ldsm4t(sb + 2 * offe(6, 16 * ks + trow, (2 * np + tck) * 8), wb0, wb1, wb2, wb3);
                    mma_bf16(O1[2*np][0], O1[2*np][1], O1[2*np][2], O1[2*np][3],
                             QA[ks][0], QA[ks][1], QA[ks][2], QA[ks][3], wb0, wb1);
                    mma_bf16(O1[2*np+1][0], O1[2*np+1][1], O1[2*np+1][2], O1[2*np+1][3],
                             QA[ks][0], QA[ks][1], QA[ks][2], QA[ks][3], wb2, wb3);
                    ldsm4t(sb + 2 * offe(7, 16 * ks + trow, (2 * np + tck) * 8), wb0, wb1, wb2, wb3);
                    mma_bf16(O2[2*np][0], O2[2*np][1], O2[2*np][2], O2[2*np][3],
                             QA[ks][0], QA[ks][1], QA[ks][2], QA[ks][3], wb0, wb1);
                    mma_bf16(O2[2*np+1][0], O2[2*np+1][1], O2[2*np+1][2], O2[2*np+1][3],
                             QA[ks][0], QA[ks][1], QA[ks][2], QA[ks][3], wb2, wb3);
                }
            }
        }

        // ---- gate + scale + store bf16 layer_out ----
        {
            int l0 = c * 64 + tlo, l1 = l0 + 8;
            float p0 = fminf(fmaxf(pi0[h * 256 + l0], 0.f), 1.f);
            float p1 = fminf(fmaxf(pi0[h * 256 + l1], 0.f), 1.f);
            size_t ro0 = ((size_t)(l0 * B_ + b)) * HD_ + h * 64;
            size_t ro1 = ((size_t)(l1 * B_ + b)) * HD_ + h * 64;
            #pragma unroll
            for (int nt = 0; nt < 8; nt++) {
                int e0 = 8 * nt + cc0;
                float f0 = SCALE_ * (O1[nt][0] * p0 + O2[nt][0] * (1.f - p0));
                float f1 = SCALE_ * (O1[nt][1] * p0 + O2[nt][1] * (1.f - p0));
                float f2 = SCALE_ * (O1[nt][2] * p1 + O2[nt][2] * (1.f - p1));
                float f3 = SCALE_ * (O1[nt][3] * p1 + O2[nt][3] * (1.f - p1));
                *(__nv_bfloat162*)&lo[ro0 + e0] = __floats2bfloat162_rn(f0, f1);
                *(__nv_bfloat162*)&lo[ro1 + e0] = __floats2bfloat162_rn(f2, f3);
            }
        }

        // ---- W += K^T V (persistent fp32 accumulators) ----
        #pragma unroll
        for (int ks = 0; ks < 4; ks++) {
            uint32_t KA1[4], KA2[4];
            ldsm4t(sb + 2 * offe(1, 16 * ks + karow, (2 * w + kack) * 8), KA1[0], KA1[1], KA1[2], KA1[3]);
            ldsm4t(sb + 2 * offe(2, 16 * ks + karow, (2 * w + kack) * 8), KA2[0], KA2[1], KA2[2], KA2[3]);
            #pragma unroll
            for (int np = 0; np < 4; np++) {
                uint32_t vb0, vb1, vb2, vb3;
                ldsm4t(sb + 2 * offe(3, 16 * ks + trow, (2 * np + tck) * 8), vb0, vb1, vb2, vb3);
                mma_bf16(W1a[2*np][0], W1a[2*np][1], W1a[2*np][2], W1a[2*np][3],
                         KA1[0], KA1[1], KA1[2], KA1[3], vb0, vb1);
                mma_bf16(W1a[2*np+1][0], W1a[2*np+1][1], W1a[2*np+1][2], W1a[2*np+1][3],
                         KA1[0], KA1[1], KA1[2], KA1[3], vb2, vb3);
                mma_bf16(W2a[2*np][0], W2a[2*np][1], W2a[2*np][2], W2a[2*np][3],
                         KA2[0], KA2[1], KA2[2], KA2[3], vb0, vb1);
                mma_bf16(W2a[2*np+1][0], W2a[2*np+1][1], W2a[2*np+1][2], W2a[2*np+1][3],
                         KA2[0], KA2[1], KA2[2], KA2[3], vb2, vb3);
            }
        }
    }
}

// ---------------- residual + LayerNorm ----------------
__global__ void __launch_bounds__(256) ln_kernel(const float* __restrict__ hin,
                                                 const float* __restrict__ attn,
                                                 const float* __restrict__ gamma,
                                                 const float* __restrict__ beta,
                                                 float* __restrict__ out)
{
    int row = blockIdx.x;
    int tid = threadIdx.x;
    const float4* hr = (const float4*)(hin  + (size_t)row * DM_);
    const float4* ar = (const float4*)(attn + (size_t)row * DM_);
    float4 hv = hr[tid], av = ar[tid];
    float x0 = hv.x + av.x, x1 = hv.y + av.y, x2 = hv.z + av.z, x3 = hv.w + av.w;
    float s  = x0 + x1 + x2 + x3;
    float sq = x0 * x0 + x1 * x1 + x2 * x2 + x3 * x3;
    int lane = tid & 31, w = tid >> 5;
    #pragma unroll
    for (int o = 16; o > 0; o >>= 1) {
        s  += __shfl_xor_sync(0xFFFFFFFFu, s,  o);
        sq += __shfl_xor_sync(0xFFFFFFFFu, sq, o);
    }
    __shared__ float rs[8], rq[8];
    if (lane == 0) { rs[w] = s; rq[w] = sq; }
    __syncthreads();
    float ts = 0.f, tq = 0.f;
    #pragma unroll
    for (int i = 0; i < 8; i++) { ts += rs[i]; tq += rq[i]; }
    float mu  = ts * (1.f / DM_);
    float var = tq * (1.f / DM_) - mu * mu;
    float inv = rsqrtf(var + LN_EPS_);

    const float4 g4 = ((const float4*)gamma)[tid];
    const float4 b4 = ((const float4*)beta)[tid];
    float4 o4;
    o4.x = (x0 - mu) * inv * g4.x + b4.x;
    o4.y = (x1 - mu) * inv * g4.y + b4.y;
    o4.z = (x2 - mu) * inv * g4.z + b4.z;
    o4.w = (x3 - mu) * inv * g4.w + b4.w;
    ((float4*)(out + (size_t)row * DM_))[tid] = o4;
}

// ---------------- launch ----------------
extern "C" void kernel_launch(void* const* d_in, const int* in_sizes, int n_in,
                              void* d_out, int out_size) {
    (void)in_sizes; (void)n_in; (void)out_size;
    const float* h      = (const float*)d_in[0];
    const float* qkv_w  = (const float*)d_in[1];
    const float* o_w    = (const float*)d_in[2];
    const float* gamma  = (const float*)d_in[3];
    const float* beta   = (const float*)d_in[4];
    const float* pi0    = (const float*)d_in[5];
    float* out = (float*)d_out;

    __nv_bfloat16 *hb, *wqkv, *wo, *lo;
    float *qb, *k1b, *k2b, *vb, *attn;
    cudaGetSymbolAddress((void**)&hb,   g_hb);
    cudaGetSymbolAddress((void**)&wqkv, g_wqkv);
    cudaGetSymbolAddress((void**)&wo,   g_wo);
    cudaGetSymbolAddress((void**)&qb,   g_q);
    cudaGetSymbolAddress((void**)&k1b,  g_k1);
    cudaGetSymbolAddress((void**)&k2b,  g_k2);
    cudaGetSymbolAddress((void**)&vb,   g_v);
    cudaGetSymbolAddress((void**)&lo,   g_lo);
    cudaGetSymbolAddress((void**)&attn, g_attn);

    cudaFuncSetAttribute(gemm_nt<0>, cudaFuncAttributeMaxDynamicSharedMemorySize, GEMM_SMEM);
    cudaFuncSetAttribute(gemm_nt<1>, cudaFuncAttributeMaxDynamicSharedMemorySize, GEMM_SMEM);
    cudaFuncSetAttribute(fw_kernel,  cudaFuncAttributeMaxDynamicSharedMemorySize, FW_SMEM);

    // casts
    cast_kernel<<<(M_*DM_/4 + 255) / 256, 256>>>(h, hb, M_*DM_/4);
    cast_kernel<<<(N1_*DM_/4 + 255) / 256, 256>>>(qkv_w, wqkv, N1_*DM_/4);
    cast_kernel<<<(DM_*HD_/4 + 255) / 256, 256>>>(o_w, wo, DM_*HD_/4);

    // QKV GEMM with scatter epilogue (raw q,k1,k2,v; phi fused into fw_kernel)
    gemm_nt<0><<<dim3(N1_/128, M_/128), 256, GEMM_SMEM>>>(hb, wqkv, M_, N1_, DM_, qb, k1b, k2b, vb);

    // fused phi + fast-weight + gate
    fw_kernel<<<B_*H_, 128, FW_SMEM>>>(pi0, lo);

    // output projection
    gemm_nt<1><<<dim3(DM_/128, M_/128), 256, GEMM_SMEM>>>(lo, wo, M_, DM_, HD_, attn, nullptr, nullptr, nullptr);

    // residual + LN
    ln_kernel<<<M_, 256>>>(h, attn, gamma, beta, out);
}

// round 3
// speedup vs baseline: 2.0351x; 1.5857x over previous
#include <cuda_runtime.h>
#include <cuda_bf16.h>
#include <cstdint>

#define H_  16
#define D_  64
#define DM_ 1024
#define L_  256
#define B_  64
#define M_  (L_*B_)       // 16384
#define N1_ (H_*4*D_)     // 4096
#define HD_ (H_*D_)       // 1024
#define SCALE_ 0.125f
#define LN_EPS_ 1e-5f

// ---------------- scratch ----------------
__device__ __nv_bfloat16 g_hb[M_*DM_];
__device__ __nv_bfloat16 g_wqkv[N1_*DM_];
__device__ __nv_bfloat16 g_wo[DM_*HD_];
__device__ float g_q [B_*H_*L_*D_];           // [B,H,L,D] pre-phi fp32
__device__ float g_k1[B_*H_*L_*D_];
__device__ float g_k2[B_*H_*L_*D_];
__device__ float g_v [B_*H_*L_*D_];
__device__ __nv_bfloat16 g_qb [B_*H_*L_*D_];  // post-phi bf16
__device__ __nv_bfloat16 g_k1b[B_*H_*L_*D_];
__device__ __nv_bfloat16 g_k2b[B_*H_*L_*D_];
__device__ __nv_bfloat16 g_vb [B_*H_*L_*D_];
__device__ __nv_bfloat16 g_lo[M_*HD_];
__device__ float g_attn[M_*DM_];

// ---------------- helpers ----------------
__global__ void cast_kernel(const float* __restrict__ in, __nv_bfloat16* __restrict__ out, int n4) {
    int i = blockIdx.x * blockDim.x + threadIdx.x;
    if (i < n4) {
        float4 f = ((const float4*)in)[i];
        __nv_bfloat162* o = ((__nv_bfloat162*)out) + i*2;
        o[0] = __floats2bfloat162_rn(f.x, f.y);
        o[1] = __floats2bfloat162_rn(f.z, f.w);
    }
}

__device__ __forceinline__ void mma_bf16(float& d0, float& d1, float& d2, float& d3,
                                         uint32_t a0, uint32_t a1, uint32_t a2, uint32_t a3,
                                         uint32_t b0, uint32_t b1) {
    asm volatile(
        "mma.sync.aligned.m16n8k16.row.col.f32.bf16.bf16.f32 "
        "{%0,%1,%2,%3},{%4,%5,%6,%7},{%8,%9},{%0,%1,%2,%3};\n"
        : "+f"(d0), "+f"(d1), "+f"(d2), "+f"(d3)
        : "r"(a0), "r"(a1), "r"(a2), "r"(a3), "r"(b0), "r"(b1));
}
__device__ __forceinline__ void ldsm4(uint32_t a, uint32_t& r0, uint32_t& r1, uint32_t& r2, uint32_t& r3) {
    asm volatile("ldmatrix.sync.aligned.m8n8.x4.shared.b16 {%0,%1,%2,%3},[%4];"
                 : "=r"(r0), "=r"(r1), "=r"(r2), "=r"(r3) : "r"(a));
}
__device__ __forceinline__ void ldsm4t(uint32_t a, uint32_t& r0, uint32_t& r1, uint32_t& r2, uint32_t& r3) {
    asm volatile("ldmatrix.sync.aligned.m8n8.x4.trans.shared.b16 {%0,%1,%2,%3},[%4];"
                 : "=r"(r0), "=r"(r1), "=r"(r2), "=r"(r3) : "r"(a));
}
#define CP_ASYNC16(dst, src) asm volatile("cp.async.cg.shared.global [%0], [%1], 16;" :: "r"(dst), "l"(src))
#define CP_COMMIT() asm volatile("cp.async.commit_group;")
#define CP_WAIT(n)  asm volatile("cp.async.wait_group %0;" :: "n"(n))

// ---------------- bf16 NT GEMM, 128x128x64, 3-stage cp.async ----------------
#define GEMM_SMEM (3 * 32768)   // 96KB: stage = A16KB + B16KB

template<int EPI>
__global__ void __launch_bounds__(256) gemm_nt(
    const __nv_bfloat16* __restrict__ A, const __nv_bfloat16* __restrict__ Bw,
    int M, int N, int K,
    float* __restrict__ o0, float* __restrict__ o1,
    float* __restrict__ o2, float* __restrict__ o3)
{
    extern __shared__ __nv_bfloat16 gsm[];
    const uint32_t smb = (uint32_t)__cvta_generic_to_shared(gsm);

    const int tid = threadIdx.x, lane = tid & 31, w = tid >> 5;
    const int wm = w & 3, wn = w >> 2;
    const int m0 = blockIdx.y * 128, n0 = blockIdx.x * 128;

    const int lr = tid >> 3, lcc = tid & 7;
    const __nv_bfloat16* Ag = A + (size_t)(m0 + lr) * K + lcc * 8;
    const __nv_bfloat16* Bg = Bw + (size_t)(n0 + lr) * K + lcc * 8;
    uint32_t stoff[4];
    #pragma unroll
    for (int g = 0; g < 4; g++) {
        int r = lr + 32 * g;
        stoff[g] = r * 128 + ((lcc ^ (r & 7)) * 16);
    }

    const int aRow = wm * 32 + ((lane >> 3) & 1) * 8 + (lane & 7);
    const int aCk  = (lane >> 4);
    const int bRow = wn * 64 + (lane >> 4) * 8 + (lane & 7);
    const int bCk  = ((lane >> 3) & 1);

    float acc[2][8][4];
    #pragma unroll
    for (int i = 0; i < 2; i++)
        #pragma unroll
        for (int j = 0; j < 8; j++)
            #pragma unroll
            for (int k = 0; k < 4; k++) acc[i][j][k] = 0.f;

    const int nk = K >> 6;

    // prologue: stages 0,1
    #pragma unroll
    for (int s = 0; s < 2; s++) {
        uint32_t ab = smb + s * 32768u, bb = ab + 16384u;
        #pragma unroll
        for (int g = 0; g < 4; g++) {
            CP_ASYNC16(ab + stoff[g], Ag + (size_t)(32 * g) * K + s * 64);
            CP_ASYNC16(bb + stoff[g], Bg + (size_t)(32 * g) * K + s * 64);
        }
        CP_COMMIT();
    }

    for (int kb = 0; kb < nk; kb++) {
        CP_WAIT(1);
        __syncthreads();
        if (kb + 2 < nk) {
            int st = (kb + 2) % 3;
            uint32_t ab = smb + st * 32768u, bb = ab + 16384u;
            #pragma unroll
            for (int g = 0; g < 4; g++) {
                CP_ASYNC16(ab + stoff[g], Ag + (size_t)(32 * g) * K + (kb + 2) * 64);
                CP_ASYNC16(bb + stoff[g], Bg + (size_t)(32 * g) * K + (kb + 2) * 64);
            }
        }
        CP_COMMIT();

        const uint32_t ab = smb + (kb % 3) * 32768u;
        const uint32_t bb = ab + 16384u;
        #pragma unroll
        for (int kk8 = 0; kk8 < 8; kk8 += 2) {
            uint32_t af[2][4], bfr[4][4];
            #pragma unroll
            for (int mt = 0; mt < 2; mt++) {
                int r = aRow + mt * 16, ck = kk8 + aCk;
                ldsm4(ab + r * 128 + ((ck ^ (r & 7)) * 16), af[mt][0], af[mt][1], af[mt][2], af[mt][3]);
            }
            #pragma unroll
            for (int np = 0; np < 4; np++) {
                int r = bRow + np * 16, ck = kk8 + bCk;
                ldsm4(bb + r * 128 + ((ck ^ (r & 7)) * 16), bfr[np][0], bfr[np][1], bfr[np][2], bfr[np][3]);
            }
            #pragma unroll
            for (int mt = 0; mt < 2; mt++)
                #pragma unroll
                for (int np = 0; np < 4; np++) {
                    mma_bf16(acc[mt][2*np][0], acc[mt][2*np][1], acc[mt][2*np][2], acc[mt][2*np][3],
                             af[mt][0], af[mt][1], af[mt][2], af[mt][3], bfr[np][0], bfr[np][1]);
                    mma_bf16(acc[mt][2*np+1][0], acc[mt][2*np+1][1], acc[mt][2*np+1][2], acc[mt][2*np+1][3],
                             af[mt][0], af[mt][1], af[mt][2], af[mt][3], bfr[np][2], bfr[np][3]);
                }
        }
    }

    // epilogue
    #pragma unroll
    for (int mt = 0; mt < 2; mt++) {
        #pragma unroll
        for (int nt = 0; nt < 8; nt++) {
            int r0 = m0 + wm * 32 + mt * 16 + (lane >> 2);
            int c0 = n0 + wn * 64 + nt * 8 + (lane & 3) * 2;
            if (EPI == 0) {
                int head = c0 >> 8;
                int part = (c0 >> 6) & 3;
                int d    = c0 & 63;
                float* bp = (part == 0) ? o0 : (part == 1) ? o1 : (part == 2) ? o2 : o3;
                #pragma unroll
                for (int rr = 0; rr < 2; rr++) {
                    int m = r0 + rr * 8;
                    int l = m >> 6, b = m & 63;
                    size_t off = (((size_t)(b * H_ + head) * L_ + l) * D_ + d);
                    *(float2*)(bp + off) = make_float2(acc[mt][nt][rr * 2], acc[mt][nt][rr * 2 + 1]);
                }
            } else {
                #pragma unroll
                for (int rr = 0; rr < 2; rr++) {
                    int m = r0 + rr * 8;
                    *(float2*)(o0 + (size_t)m * N + c0) = make_float2(acc[mt][nt][rr * 2], acc[mt][nt][rr * 2 + 1]);
                }
            }
        }
    }
}

// ---------------- phi pass: fp32 -> phi -> bf16 (and plain cast for v) ----------------
__global__ void __launch_bounds__(256) phi_kernel() {
    int t = blockIdx.y;
    const float* src = (t == 0) ? g_q : (t == 1) ? g_k1 : (t == 2) ? g_k2 : g_v;
    __nv_bfloat16* dst = (t == 0) ? g_qb : (t == 1) ? g_k1b : (t == 2) ? g_k2b : g_vb;
    int row  = blockIdx.x * 8 + (threadIdx.x >> 5);
    int lane = threadIdx.x & 31;
    float2 xv = *(const float2*)(src + (size_t)row * 64 + 2 * lane);
    if (t < 3) {
        float e0 = (xv.x > 0.f) ? (xv.x + 1.f) : __expf(xv.x);
        float e1 = (xv.y > 0.f) ? (xv.y + 1.f) : __expf(xv.y);
        float s = e0 + e1;
        #pragma unroll
        for (int o = 16; o > 0; o >>= 1) s += __shfl_xor_sync(0xFFFFFFFFu, s, o);
        float inv = 1.f / s;
        xv.x = e0 * inv; xv.y = e1 * inv;
    }
    *(__nv_bfloat162*)(dst + (size_t)row * 64 + 2 * lane) = __floats2bfloat162_rn(xv.x, xv.y);
}

// ---------------- fast-weight: 256 thr, memory-split groups, cp.async double buffer ----------------
// tiles (4096 bf16 each): 0-3 = buf0 {Q,K1,K2,V}, 4-7 = buf1, 8=S1, 9=S2/exchange, 10=W1, 11=W2
#define FW_SMEM (12 * 4096 * 2)   // 96KB

__device__ __forceinline__ int offe(int t, int r, int c) {
    return t * 4096 + r * 64 + ((((c >> 3) ^ (r & 7))) << 3) + (c & 7);
}

__global__ void __launch_bounds__(256) fw_kernel(const float* __restrict__ pi0,
                                                 __nv_bfloat16* __restrict__ lo)
{
    extern __shared__ __nv_bfloat16 fs[];
    const uint32_t sb = (uint32_t)__cvta_generic_to_shared(fs);
    const int bh = blockIdx.x, b = bh >> 4, h = bh & 15;
    const int tid = threadIdx.x, lane = tid & 31, warp = tid >> 5;
    const int g = warp >> 2, wg = warp & 3;
    const size_t base = (size_t)bh * (L_ * D_);
    const __nv_bfloat16* srcs[4] = { g_qb + base, g_k1b + base, g_k2b + base, g_vb + base };

    const int lr = tid >> 3, lcc = tid & 7;

    const int arow = 16 * wg + ((lane >> 3) & 1) * 8 + (lane & 7);
    const int ac0  = (lane >> 4);
    const int brow = (lane >> 4) * 8 + (lane & 7);
    const int bck  = ((lane >> 3) & 1);
    const int trow = ((lane >> 3) & 1) * 8 + (lane & 7);
    const int tck  = (lane >> 4);
    const int karow = (lane >> 4) * 8 + (lane & 7);
    const int kack  = ((lane >> 3) & 1);
    const int tlo = 16 * wg + (lane >> 2);
    const int cc0 = (lane & 3) * 2;

    float Wa[8][4], O[8][4];
    #pragma unroll
    for (int n = 0; n < 8; n++)
        #pragma unroll
        for (int q = 0; q < 4; q++) Wa[n][q] = 0.f;

    // issue chunk 0 into buf 0
    #pragma unroll
    for (int t = 0; t < 4; t++) {
        const __nv_bfloat16* sp = srcs[t];
        #pragma unroll
        for (int g2 = 0; g2 < 2; g2++) {
            int r = lr + 32 * g2;
            CP_ASYNC16(sb + 2u * offe(t, r, lcc * 8), sp + r * 64 + lcc * 8);
        }
    }
    CP_COMMIT();

    for (int c = 0; c < 4; c++) {
        __syncthreads();   // all warps done with previous chunk's tiles
        if (c + 1 < 4) {
            int s4 = ((c + 1) & 1) * 4;
            #pragma unroll
            for (int t = 0; t < 4; t++) {
                const __nv_bfloat16* sp = srcs[t] + (c + 1) * 4096;
                #pragma unroll
                for (int g2 = 0; g2 < 2; g2++) {
                    int r = lr + 32 * g2;
                    CP_ASYNC16(sb + 2u * offe(s4 + t, r, lcc * 8), sp + r * 64 + lcc * 8);
                }
            }
        }
        CP_COMMIT();
        CP_WAIT(1);

        // stage W accum -> bf16 tile 10+g
        if (c) {
            #pragma unroll
            for (int n = 0; n < 8; n++) {
                #pragma unroll
                for (int hf = 0; hf < 2; hf++) {
                    int r = 16 * wg + (lane >> 2) + 8 * hf;
                    *(__nv_bfloat162*)&fs[offe(10 + g, r, 8 * n + cc0)] =
                        __floats2bfloat162_rn(Wa[n][2*hf], Wa[n][2*hf+1]);
                }
            }
        }
        __syncthreads();

        const int tb = (c & 1) * 4;

        // Q A-fragments
        uint32_t QA[4][4];
        #pragma unroll
        for (int ks = 0; ks < 4; ks++)
            ldsm4(sb + 2u * offe(tb + 0, arow, (2 * ks + ac0) * 8), QA[ks][0], QA[ks][1], QA[ks][2], QA[ks][3]);

        // S(g) = Q K(g)^T
        #pragma unroll
        for (int n = 0; n < 8; n++)
            #pragma unroll
            for (int q = 0; q < 4; q++) O[n][q] = 0.f;
        #pragma unroll
        for (int ks = 0; ks < 4; ks++)
            #pragma unroll
            for (int np = 0; np < 4; np++) {
                uint32_t b0, b1, b2, b3;
                ldsm4(sb + 2u * offe(tb + 1 + g, 16 * np + brow, (2 * ks + bck) * 8), b0, b1, b2, b3);
                mma_bf16(O[2*np][0], O[2*np][1], O[2*np][2], O[2*np][3],
                         QA[ks][0], QA[ks][1], QA[ks][2], QA[ks][3], b0, b1);
                mma_bf16(O[2*np+1][0], O[2*np+1][1], O[2*np+1][2], O[2*np+1][3],
                         QA[ks][0], QA[ks][1], QA[ks][2], QA[ks][3], b2, b3);
            }

        // masked store S(g) -> tile 8+g, reset acc
        #pragma unroll
        for (int nt = 0; nt < 8; nt++) {
            int s0 = 8 * nt + cc0;
            float v0 = (s0     <= tlo) ? O[nt][0] : 0.f;
            float v1 = (s0 + 1 <= tlo) ? O[nt][1] : 0.f;
            float v2 = (s0     <= tlo + 8) ? O[nt][2] : 0.f;
            float v3 = (s0 + 1 <= tlo + 8) ? O[nt][3] : 0.f;
            *(__nv_bfloat162*)&fs[offe(8 + g, tlo, s0)]     = __floats2bfloat162_rn(v0, v1);
            *(__nv_bfloat162*)&fs[offe(8 + g, tlo + 8, s0)] = __floats2bfloat162_rn(v2, v3);
            #pragma unroll
            for (int q = 0; q < 4; q++) O[nt][q] = 0.f;
        }
        __syncwarp();

        // O(g) = S(g)@V + Q@W(g)
        #pragma unroll
        for (int ks = 0; ks < 4; ks++) {
            uint32_t SA[4];
            ldsm4(sb + 2u * offe(8 + g, arow, (2 * ks + ac0) * 8), SA[0], SA[1], SA[2], SA[3]);
            #pragma unroll
            for (int np = 0; np < 4; np++) {
                uint32_t vb0, vb1, vb2, vb3;
                ldsm4t(sb + 2u * offe(tb + 3, 16 * ks + trow, (2 * np + tck) * 8), vb0, vb1, vb2, vb3);
                mma_bf16(O[2*np][0], O[2*np][1], O[2*np][2], O[2*np][3],
                         SA[0], SA[1], SA[2], SA[3], vb0, vb1);
                mma_bf16(O[2*np+1][0], O[2*np+1][1], O[2*np+1][2], O[2*np+1][3],
                         SA[0], SA[1], SA[2], SA[3], vb2, vb3);
                if (c) {
                    uint32_t wb0, wb1, wb2, wb3;
                    ldsm4t(sb + 2u * offe(10 + g, 16 * ks + trow, (2 * np + tck) * 8), wb0, wb1, wb2, wb3);
                    mma_bf16(O[2*np][0], O[2*np][1], O[2*np][2], O[2*np][3],
                             QA[ks][0], QA[ks][1], QA[ks][2], QA[ks][3], wb0, wb1);
                    mma_bf16(O[2*np+1][0], O[2*np+1][1], O[2*np+1][2], O[2*np+1][3],
                             QA[ks][0], QA[ks][1], QA[ks][2], QA[ks][3], wb2, wb3);
                }
            }
        }

        // gate: group1 writes SCALE*(1-p)*O2 into exchange tile 9; group0 combines + stores
        {
            int l0 = c * 64 + tlo, l1 = l0 + 8;
            float p0 = fminf(fmaxf(pi0[h * 256 + l0], 0.f), 1.f);
            float p1 = fminf(fmaxf(pi0[h * 256 + l1], 0.f), 1.f);
            if (g == 1) {
                float q0 = SCALE_ * (1.f - p0), q1 = SCALE_ * (1.f - p1);
                #pragma unroll
                for (int nt = 0; nt < 8; nt++) {
                    int s0 = 8 * nt + cc0;
                    *(__nv_bfloat162*)&fs[offe(9, tlo, s0)]     = __floats2bfloat162_rn(q0 * O[nt][0], q0 * O[nt][1]);
                    *(__nv_bfloat162*)&fs[offe(9, tlo + 8, s0)] = __floats2bfloat162_rn(q1 * O[nt][2], q1 * O[nt][3]);
                }
            }
            __syncthreads();
            if (g == 0) {
                float q0 = SCALE_ * p0, q1 = SCALE_ * p1;
                size_t ro0 = ((size_t)(l0 * B_ + b)) * HD_ + h * 64;
                size_t ro1 = ((size_t)(l1 * B_ + b)) * HD_ + h * 64;
                #pragma unroll
                for (int nt = 0; nt < 8; nt++) {
                    int e0 = 8 * nt + cc0;
                    __nv_bfloat162 x0 = *(__nv_bfloat162*)&fs[offe(9, tlo, e0)];
                    __nv_bfloat162 x1 = *(__nv_bfloat162*)&fs[offe(9, tlo + 8, e0)];
                    float f0 = q0 * O[nt][0] + __bfloat162float(x0.x);
                    float f1 = q0 * O[nt][1] + __bfloat162float(x0.y);
                    float f2 = q1 * O[nt][2] + __bfloat162float(x1.x);
                    float f3 = q1 * O[nt][3] + __bfloat162float(x1.y);
                    *(__nv_bfloat162*)&lo[ro0 + e0] = __floats2bfloat162_rn(f0, f1);
                    *(__nv_bfloat162*)&lo[ro1 + e0] = __floats2bfloat162_rn(f2, f3);
                }
            }
        }

        // W(g) += K(g)^T V
        #pragma unroll
        for (int ks = 0; ks < 4; ks++) {
            uint32_t KA[4];
            ldsm4t(sb + 2u * offe(tb + 1 + g, 16 * ks + karow, (2 * wg + kack) * 8), KA[0], KA[1], KA[2], KA[3]);
            #pragma unroll
            for (int np = 0; np < 4; np++) {
                uint32_t vb0, vb1, vb2, vb3;
                ldsm4t(sb + 2u * offe(tb + 3, 16 * ks + trow, (2 * np + tck) * 8), vb0, vb1, vb2, vb3);
                mma_bf16(Wa[2*np][0], Wa[2*np][1], Wa[2*np][2], Wa[2*np][3],
                         KA[0], KA[1], KA[2], KA[3], vb0, vb1);
                mma_bf16(Wa[2*np+1][0], Wa[2*np+1][1], Wa[2*np+1][2], Wa[2*np+1][3],
                         KA[0], KA[1], KA[2], KA[3], vb2, vb3);
            }
        }
    }
}

// ---------------- residual + LayerNorm ----------------
__global__ void __launch_bounds__(256) ln_kernel(const float* __restrict__ hin,
                                                 const float* __restrict__ attn,
                                                 const float* __restrict__ gamma,
                                                 const float* __restrict__ beta,
                                                 float* __restrict__ out)
{
    int row = blockIdx.x;
    int tid = threadIdx.x;
    const float4* hr = (const float4*)(hin  + (size_t)row * DM_);
    const float4* ar = (const float4*)(attn + (size_t)row * DM_);
    float4 hv = hr[tid], av = ar[tid];
    float x0 = hv.x + av.x, x1 = hv.y + av.y, x2 = hv.z + av.z, x3 = hv.w + av.w;
    float s  = x0 + x1 + x2 + x3;
    float sq = x0 * x0 + x1 * x1 + x2 * x2 + x3 * x3;
    int lane = tid & 31, w = tid >> 5;
    #pragma unroll
    for (int o = 16; o > 0; o >>= 1) {
        s  += __shfl_xor_sync(0xFFFFFFFFu, s,  o);
        sq += __shfl_xor_sync(0xFFFFFFFFu, sq, o);
    }
    __shared__ float rs[8], rq[8];
    if (lane == 0) { rs[w] = s; rq[w] = sq; }
    __syncthreads();
    float ts = 0.f, tq = 0.f;
    #pragma unroll
    for (int i = 0; i < 8; i++) { ts += rs[i]; tq += rq[i]; }
    float mu  = ts * (1.f / DM_);
    float var = tq * (1.f / DM_) - mu * mu;
    float inv = rsqrtf(var + LN_EPS_);
    const float4 g4 = ((const float4*)gamma)[tid];
    const float4 b4 = ((const float4*)beta)[tid];
    float4 o4;
    o4.x = (x0 - mu) * inv * g4.x + b4.x;
    o4.y = (x1 - mu) * inv * g4.y + b4.y;
    o4.z = (x2 - mu) * inv * g4.z + b4.z;
    o4.w = (x3 - mu) * inv * g4.w + b4.w;
    ((float4*)(out + (size_t)row * DM_))[tid] = o4;
}

// ---------------- launch ----------------
extern "C" void kernel_launch(void* const* d_in, const int* in_sizes, int n_in,
                              void* d_out, int out_size) {
    (void)in_sizes; (void)n_in; (void)out_size;
    const float* h      = (const float*)d_in[0];
    const float* qkv_w  = (const float*)d_in[1];
    const float* o_w    = (const float*)d_in[2];
    const float* gamma  = (const float*)d_in[3];
    const float* beta   = (const float*)d_in[4];
    const float* pi0    = (const float*)d_in[5];
    float* out = (float*)d_out;

    __nv_bfloat16 *hb, *wqkv, *wo, *lo;
    float *qb, *k1b, *k2b, *vb, *attn;
    cudaGetSymbolAddress((void**)&hb,   g_hb);
    cudaGetSymbolAddress((void**)&wqkv, g_wqkv);
    cudaGetSymbolAddress((void**)&wo,   g_wo);
    cudaGetSymbolAddress((void**)&qb,   g_q);
    cudaGetSymbolAddress((void**)&k1b,  g_k1);
    cudaGetSymbolAddress((void**)&k2b,  g_k2);
    cudaGetSymbolAddress((void**)&vb,   g_v);
    cudaGetSymbolAddress((void**)&lo,   g_lo);
    cudaGetSymbolAddress((void**)&attn, g_attn);

    cudaFuncSetAttribute(gemm_nt<0>, cudaFuncAttributeMaxDynamicSharedMemorySize, GEMM_SMEM);
    cudaFuncSetAttribute(gemm_nt<1>, cudaFuncAttributeMaxDynamicSharedMemorySize, GEMM_SMEM);
    cudaFuncSetAttribute(fw_kernel,  cudaFuncAttributeMaxDynamicSharedMemorySize, FW_SMEM);

    cast_kernel<<<(M_*DM_/4 + 255) / 256, 256>>>(h, hb, M_*DM_/4);
    cast_kernel<<<(N1_*DM_/4 + 255) / 256, 256>>>(qkv_w, wqkv, N1_*DM_/4);
    cast_kernel<<<(DM_*HD_/4 + 255) / 256, 256>>>(o_w, wo, DM_*HD_/4);

    gemm_nt<0><<<dim3(N1_/128, M_/128), 256, GEMM_SMEM>>>(hb, wqkv, M_, N1_, DM_, qb, k1b, k2b, vb);

    phi_kernel<<<dim3((B_*H_*L_)/8, 4), 256>>>();

    fw_kernel<<<B_*H_, 256, FW_SMEM>>>(pi0, lo);

    gemm_nt<1><<<dim3(DM_/128, M_/128), 256, GEMM_SMEM>>>(lo, wo, M_, DM_, HD_, attn, nullptr, nullptr, nullptr);

    ln_kernel<<<M_, 256>>>(h, attn, gamma, beta, out);
}

// round 5
// speedup vs baseline: 2.4152x; 1.1867x over previous
#include <cuda_runtime.h>
#include <cuda_bf16.h>
#include <cstdint>

#define H_  16
#define D_  64
#define DM_ 1024
#define L_  256
#define B_  64
#define M_  (L_*B_)       // 16384
#define N1_ (H_*4*D_)     // 4096
#define HD_ (H_*D_)       // 1024
#define SCALE_ 0.125f
#define LN_EPS_ 1e-5f

// ---------------- scratch ----------------
__device__ __nv_bfloat16 g_hb[M_*DM_];
__device__ __nv_bfloat16 g_wqkv[N1_*DM_];
__device__ __nv_bfloat16 g_wo[DM_*HD_];
__device__ __nv_bfloat16 g_qb [B_*H_*L_*D_];  // post-phi bf16 [B,H,L,D]
__device__ __nv_bfloat16 g_k1b[B_*H_*L_*D_];
__device__ __nv_bfloat16 g_k2b[B_*H_*L_*D_];
__device__ __nv_bfloat16 g_vb [B_*H_*L_*D_];
__device__ __nv_bfloat16 g_lo[M_*HD_];        // gated layer_out
__device__ __nv_bfloat16 g_attnb[M_*DM_];     // attn_out bf16

// ---------------- helpers ----------------
__global__ void cast_kernel(const float* __restrict__ in, __nv_bfloat16* __restrict__ out, int n4) {
    int i = blockIdx.x * blockDim.x + threadIdx.x;
    if (i < n4) {
        float4 f = ((const float4*)in)[i];
        __nv_bfloat162* o = ((__nv_bfloat162*)out) + i*2;
        o[0] = __floats2bfloat162_rn(f.x, f.y);
        o[1] = __floats2bfloat162_rn(f.z, f.w);
    }
}

__device__ __forceinline__ void mma_bf16(float& d0, float& d1, float& d2, float& d3,
                                         uint32_t a0, uint32_t a1, uint32_t a2, uint32_t a3,
                                         uint32_t b0, uint32_t b1) {
    asm volatile(
        "mma.sync.aligned.m16n8k16.row.col.f32.bf16.bf16.f32 "
        "{%0,%1,%2,%3},{%4,%5,%6,%7},{%8,%9},{%0,%1,%2,%3};\n"
        : "+f"(d0), "+f"(d1), "+f"(d2), "+f"(d3)
        : "r"(a0), "r"(a1), "r"(a2), "r"(a3), "r"(b0), "r"(b1));
}
__device__ __forceinline__ void ldsm4(uint32_t a, uint32_t& r0, uint32_t& r1, uint32_t& r2, uint32_t& r3) {
    asm volatile("ldmatrix.sync.aligned.m8n8.x4.shared.b16 {%0,%1,%2,%3},[%4];"
                 : "=r"(r0), "=r"(r1), "=r"(r2), "=r"(r3) : "r"(a));
}
__device__ __forceinline__ void ldsm4t(uint32_t a, uint32_t& r0, uint32_t& r1, uint32_t& r2, uint32_t& r3) {
    asm volatile("ldmatrix.sync.aligned.m8n8.x4.trans.shared.b16 {%0,%1,%2,%3},[%4];"
                 : "=r"(r0), "=r"(r1), "=r"(r2), "=r"(r3) : "r"(a));
}
#define CP_ASYNC16(dst, src) asm volatile("cp.async.cg.shared.global [%0], [%1], 16;" :: "r"(dst), "l"(src))
#define CP_COMMIT() asm volatile("cp.async.commit_group;")
#define CP_WAIT(n)  asm volatile("cp.async.wait_group %0;" :: "n"(n))

// ---------------- bf16 NT GEMM, 128x128x64, 3-stage cp.async ----------------
// EPI=0: fused-phi epilogue -> bf16 q/k1/k2/v in [B,H,L,D]. EPI=1: bf16 row-major C.
#define GEMM_SMEM (3 * 32768)   // 96KB

template<int EPI>
__global__ void __launch_bounds__(256) gemm_nt(
    const __nv_bfloat16* __restrict__ A, const __nv_bfloat16* __restrict__ Bw,
    int M, int N, int K, __nv_bfloat16* __restrict__ outp)
{
    extern __shared__ __nv_bfloat16 gsm[];
    const uint32_t smb = (uint32_t)__cvta_generic_to_shared(gsm);

    const int tid = threadIdx.x, lane = tid & 31, w = tid >> 5;
    const int wm = w & 3, wn = w >> 2;
    const int m0 = blockIdx.y * 128, n0 = blockIdx.x * 128;

    const int lr = tid >> 3, lcc = tid & 7;
    const __nv_bfloat16* Ag = A + (size_t)(m0 + lr) * K + lcc * 8;
    const __nv_bfloat16* Bg = Bw + (size_t)(n0 + lr) * K + lcc * 8;
    uint32_t stoff[4];
    #pragma unroll
    for (int g = 0; g < 4; g++) {
        int r = lr + 32 * g;
        stoff[g] = r * 128 + ((lcc ^ (r & 7)) * 16);
    }

    const int aRow = wm * 32 + ((lane >> 3) & 1) * 8 + (lane & 7);
    const int aCk  = (lane >> 4);
    const int bRow = wn * 64 + (lane >> 4) * 8 + (lane & 7);
    const int bCk  = ((lane >> 3) & 1);

    float acc[2][8][4];
    #pragma unroll
    for (int i = 0; i < 2; i++)
        #pragma unroll
        for (int j = 0; j < 8; j++)
            #pragma unroll
            for (int k = 0; k < 4; k++) acc[i][j][k] = 0.f;

    const int nk = K >> 6;

    #pragma unroll
    for (int s = 0; s < 2; s++) {
        uint32_t ab = smb + s * 32768u, bb = ab + 16384u;
        #pragma unroll
        for (int g = 0; g < 4; g++) {
            CP_ASYNC16(ab + stoff[g], Ag + (size_t)(32 * g) * K + s * 64);
            CP_ASYNC16(bb + stoff[g], Bg + (size_t)(32 * g) * K + s * 64);
        }
        CP_COMMIT();
    }

    for (int kb = 0; kb < nk; kb++) {
        CP_WAIT(1);
        __syncthreads();
        if (kb + 2 < nk) {
            int st = (kb + 2) % 3;
            uint32_t ab = smb + st * 32768u, bb = ab + 16384u;
            #pragma unroll
            for (int g = 0; g < 4; g++) {
                CP_ASYNC16(ab + stoff[g], Ag + (size_t)(32 * g) * K + (kb + 2) * 64);
                CP_ASYNC16(bb + stoff[g], Bg + (size_t)(32 * g) * K + (kb + 2) * 64);
            }
        }
        CP_COMMIT();

        const uint32_t ab = smb + (kb % 3) * 32768u;
        const uint32_t bb = ab + 16384u;
        #pragma unroll
        for (int kk8 = 0; kk8 < 8; kk8 += 2) {
            uint32_t af[2][4], bfr[4][4];
            #pragma unroll
            for (int mt = 0; mt < 2; mt++) {
                int r = aRow + mt * 16, ck = kk8 + aCk;
                ldsm4(ab + r * 128 + ((ck ^ (r & 7)) * 16), af[mt][0], af[mt][1], af[mt][2], af[mt][3]);
            }
            #pragma unroll
            for (int np = 0; np < 4; np++) {
                int r = bRow + np * 16, ck = kk8 + bCk;
                ldsm4(bb + r * 128 + ((ck ^ (r & 7)) * 16), bfr[np][0], bfr[np][1], bfr[np][2], bfr[np][3]);
            }
            #pragma unroll
            for (int mt = 0; mt < 2; mt++)
                #pragma unroll
                for (int np = 0; np < 4; np++) {
                    mma_bf16(acc[mt][2*np][0], acc[mt][2*np][1], acc[mt][2*np][2], acc[mt][2*np][3],
                             af[mt][0], af[mt][1], af[mt][2], af[mt][3], bfr[np][0], bfr[np][1]);
                    mma_bf16(acc[mt][2*np+1][0], acc[mt][2*np+1][1], acc[mt][2*np+1][2], acc[mt][2*np+1][3],
                             af[mt][0], af[mt][1], af[mt][2], af[mt][3], bfr[np][2], bfr[np][3]);
                }
        }
    }

    // ---------------- epilogue ----------------
    if (EPI == 0) {
        // whole warp tile sits in one (head, part) 64-col segment
        const int c0base = n0 + wn * 64;
        const int head = c0base >> 8, part = (c0base >> 6) & 3;
        __nv_bfloat16* dst = (part == 0) ? g_qb : (part == 1) ? g_k1b
                           : (part == 2) ? g_k2b : g_vb;
        #pragma unroll
        for (int mt = 0; mt < 2; mt++) {
            #pragma unroll
            for (int rr = 0; rr < 2; rr++) {
                // this thread holds 16 of the 64 cols of row m (quad covers all 64)
                int m = m0 + wm * 32 + mt * 16 + (lane >> 2) + rr * 8;
                float v[16];
                #pragma unroll
                for (int nt = 0; nt < 8; nt++) {
                    v[2*nt]   = acc[mt][nt][rr*2];
                    v[2*nt+1] = acc[mt][nt][rr*2+1];
                }
                float inv = 1.f;
                if (part < 3) {
                    float s = 0.f;
                    #pragma unroll
                    for (int i = 0; i < 16; i++) {
                        v[i] = (v[i] > 0.f) ? (v[i] + 1.f) : __expf(v[i]);
                        s += v[i];
                    }
                    s += __shfl_xor_sync(0xFFFFFFFFu, s, 1);
                    s += __shfl_xor_sync(0xFFFFFFFFu, s, 2);
                    inv = 1.f / s;
                }
                int l = m >> 6, b = m & 63;
                __nv_bfloat16* rowp = dst + (((size_t)(b * H_ + head) * L_ + l) << 6);
                #pragma unroll
                for (int nt = 0; nt < 8; nt++) {
                    int cc = nt * 8 + (lane & 3) * 2;
                    *(__nv_bfloat162*)(rowp + cc) = __floats2bfloat162_rn(v[2*nt] * inv, v[2*nt+1] * inv);
                }
            }
        }
    } else {
        #pragma unroll
        for (int mt = 0; mt < 2; mt++) {
            #pragma unroll
            for (int nt = 0; nt < 8; nt++) {
                int r0 = m0 + wm * 32 + mt * 16 + (lane >> 2);
                int c0 = n0 + wn * 64 + nt * 8 + (lane & 3) * 2;
                #pragma unroll
                for (int rr = 0; rr < 2; rr++) {
                    int m = r0 + rr * 8;
                    *(__nv_bfloat162*)(outp + (size_t)m * N + c0) =
                        __floats2bfloat162_rn(acc[mt][nt][rr*2], acc[mt][nt][rr*2+1]);
                }
            }
        }
    }
}

// ---------------- fast-weight: 256 thr, memory-split groups, cp.async double buffer ----------------
#define FW_SMEM (12 * 4096 * 2)   // 96KB

__device__ __forceinline__ int offe(int t, int r, int c) {
    return t * 4096 + r * 64 + ((((c >> 3) ^ (r & 7))) << 3) + (c & 7);
}

__global__ void __launch_bounds__(256) fw_kernel(const float* __restrict__ pi0,
                                                 __nv_bfloat16* __restrict__ lo)
{
    extern __shared__ __nv_bfloat16 fs[];
    const uint32_t sb = (uint32_t)__cvta_generic_to_shared(fs);
    const int bh = blockIdx.x, b = bh >> 4, h = bh & 15;
    const int tid = threadIdx.x, lane = tid & 31, warp = tid >> 5;
    const int g = warp >> 2, wg = warp & 3;
    const size_t base = (size_t)bh * (L_ * D_);
    const __nv_bfloat16* srcs[4] = { g_qb + base, g_k1b + base, g_k2b + base, g_vb + base };

    const int lr = tid >> 3, lcc = tid & 7;

    const int arow = 16 * wg + ((lane >> 3) & 1) * 8 + (lane & 7);
    const int ac0  = (lane >> 4);
    const int brow = (lane >> 4) * 8 + (lane & 7);
    const int bck  = ((lane >> 3) & 1);
    const int trow = ((lane >> 3) & 1) * 8 + (lane & 7);
    const int tck  = (lane >> 4);
    const int karow = (lane >> 4) * 8 + (lane & 7);
    const int kack  = ((lane >> 3) & 1);
    const int tlo = 16 * wg + (lane >> 2);
    const int cc0 = (lane & 3) * 2;

    float Wa[8][4], O[8][4];
    #pragma unroll
    for (int n = 0; n < 8; n++)
        #pragma unroll
        for (int q = 0; q < 4; q++) Wa[n][q] = 0.f;

    #pragma unroll
    for (int t = 0; t < 4; t++) {
        const __nv_bfloat16* sp = srcs[t];
        #pragma unroll
        for (int g2 = 0; g2 < 2; g2++) {
            int r = lr + 32 * g2;
            CP_ASYNC16(sb + 2u * offe(t, r, lcc * 8), sp + r * 64 + lcc * 8);
        }
    }
    CP_COMMIT();

    for (int c = 0; c < 4; c++) {
        __syncthreads();
        if (c + 1 < 4) {
            int s4 = ((c + 1) & 1) * 4;
            #pragma unroll
            for (int t = 0; t < 4; t++) {
                const __nv_bfloat16* sp = srcs[t] + (c + 1) * 4096;
                #pragma unroll
                for (int g2 = 0; g2 < 2; g2++) {
                    int r = lr + 32 * g2;
                    CP_ASYNC16(sb + 2u * offe(s4 + t, r, lcc * 8), sp + r * 64 + lcc * 8);
                }
            }
        }
        CP_COMMIT();
        CP_WAIT(1);

        if (c) {
            #pragma unroll
            for (int n = 0; n < 8; n++) {
                #pragma unroll
                for (int hf = 0; hf < 2; hf++) {
                    int r = 16 * wg + (lane >> 2) + 8 * hf;
                    *(__nv_bfloat162*)&fs[offe(10 + g, r, 8 * n + cc0)] =
                        __floats2bfloat162_rn(Wa[n][2*hf], Wa[n][2*hf+1]);
                }
            }
        }
        __syncthreads();

        const int tb = (c & 1) * 4;

        uint32_t QA[4][4];
        #pragma unroll
        for (int ks = 0; ks < 4; ks++)
            ldsm4(sb + 2u * offe(tb + 0, arow, (2 * ks + ac0) * 8), QA[ks][0], QA[ks][1], QA[ks][2], QA[ks][3]);

        #pragma unroll
        for (int n = 0; n < 8; n++)
            #pragma unroll
            for (int q = 0; q < 4; q++) O[n][q] = 0.f;
        #pragma unroll
        for (int ks = 0; ks < 4; ks++)
            #pragma unroll
            for (int np = 0; np < 4; np++) {
                uint32_t b0, b1, b2, b3;
                ldsm4(sb + 2u * offe(tb + 1 + g, 16 * np + brow, (2 * ks + bck) * 8), b0, b1, b2, b3);
                mma_bf16(O[2*np][0], O[2*np][1], O[2*np][2], O[2*np][3],
                         QA[ks][0], QA[ks][1], QA[ks][2], QA[ks][3], b0, b1);
                mma_bf16(O[2*np+1][0], O[2*np+1][1], O[2*np+1][2], O[2*np+1][3],
                         QA[ks][0], QA[ks][1], QA[ks][2], QA[ks][3], b2, b3);
            }

        #pragma unroll
        for (int nt = 0; nt < 8; nt++) {
            int s0 = 8 * nt + cc0;
            float v0 = (s0     <= tlo) ? O[nt][0] : 0.f;
            float v1 = (s0 + 1 <= tlo) ? O[nt][1] : 0.f;
            float v2 = (s0     <= tlo + 8) ? O[nt][2] : 0.f;
            float v3 = (s0 + 1 <= tlo + 8) ? O[nt][3] : 0.f;
            *(__nv_bfloat162*)&fs[offe(8 + g, tlo, s0)]     = __floats2bfloat162_rn(v0, v1);
            *(__nv_bfloat162*)&fs[offe(8 + g, tlo + 8, s0)] = __floats2bfloat162_rn(v2, v3);
            #pragma unroll
            for (int q = 0; q < 4; q++) O[nt][q] = 0.f;
        }
        __syncwarp();

        #pragma unroll
        for (int ks = 0; ks < 4; ks++) {
            uint32_t SA[4];
            ldsm4(sb + 2u * offe(8 + g, arow, (2 * ks + ac0) * 8), SA[0], SA[1], SA[2], SA[3]);
            #pragma unroll
            for (int np = 0; np < 4; np++) {
                uint32_t vb0, vb1, vb2, vb3;
                ldsm4t(sb + 2u * offe(tb + 3, 16 * ks + trow, (2 * np + tck) * 8), vb0, vb1, vb2, vb3);
                mma_bf16(O[2*np][0], O[2*np][1], O[2*np][2], O[2*np][3],
                         SA[0], SA[1], SA[2], SA[3], vb0, vb1);
                mma_bf16(O[2*np+1][0], O[2*np+1][1], O[2*np+1][2], O[2*np+1][3],
                         SA[0], SA[1], SA[2], SA[3], vb2, vb3);
                if (c) {
                    uint32_t wb0, wb1, wb2, wb3;
                    ldsm4t(sb + 2u * offe(10 + g, 16 * ks + trow, (2 * np + tck) * 8), wb0, wb1, wb2, wb3);
                    mma_bf16(O[2*np][0], O[2*np][1], O[2*np][2], O[2*np][3],
                             QA[ks][0], QA[ks][1], QA[ks][2], QA[ks][3], wb0, wb1);
                    mma_bf16(O[2*np+1][0], O[2*np+1][1], O[2*np+1][2], O[2*np+1][3],
                             QA[ks][0], QA[ks][1], QA[ks][2], QA[ks][3], wb2, wb3);
                }
            }
        }

        {
            int l0 = c * 64 + tlo, l1 = l0 + 8;
            float p0 = fminf(fmaxf(pi0[h * 256 + l0], 0.f), 1.f);
            float p1 = fminf(fmaxf(pi0[h * 256 + l1], 0.f), 1.f);
            if (g == 1) {
                float q0 = SCALE_ * (1.f - p0), q1 = SCALE_ * (1.f - p1);
                #pragma unroll
                for (int nt = 0; nt < 8; nt++) {
                    int s0 = 8 * nt + cc0;
                    *(__nv_bfloat162*)&fs[offe(9, tlo, s0)]     = __floats2bfloat162_rn(q0 * O[nt][0], q0 * O[nt][1]);
                    *(__nv_bfloat162*)&fs[offe(9, tlo + 8, s0)] = __floats2bfloat162_rn(q1 * O[nt][2], q1 * O[nt][3]);
                }
            }
            __syncthreads();
            if (g == 0) {
                float q0 = SCALE_ * p0, q1 = SCALE_ * p1;
                size_t ro0 = ((size_t)(l0 * B_ + b)) * HD_ + h * 64;
                size_t ro1 = ((size_t)(l1 * B_ + b)) * HD_ + h * 64;
                #pragma unroll
                for (int nt = 0; nt < 8; nt++) {
                    int e0 = 8 * nt + cc0;
                    __nv_bfloat162 x0 = *(__nv_bfloat162*)&fs[offe(9, tlo, e0)];
                    __nv_bfloat162 x1 = *(__nv_bfloat162*)&fs[offe(9, tlo + 8, e0)];
                    float f0 = q0 * O[nt][0] + __bfloat162float(x0.x);
                    float f1 = q0 * O[nt][1] + __bfloat162float(x0.y);
                    float f2 = q1 * O[nt][2] + __bfloat162float(x1.x);
                    float f3 = q1 * O[nt][3] + __bfloat162float(x1.y);
                    *(__nv_bfloat162*)&lo[ro0 + e0] = __floats2bfloat162_rn(f0, f1);
                    *(__nv_bfloat162*)&lo[ro1 + e0] = __floats2bfloat162_rn(f2, f3);
                }
            }
        }

        #pragma unroll
        for (int ks = 0; ks < 4; ks++) {
            uint32_t KA[4];
            ldsm4t(sb + 2u * offe(tb + 1 + g, 16 * ks + karow, (2 * wg + kack) * 8), KA[0], KA[1], KA[2], KA[3]);
            #pragma unroll
            for (int np = 0; np < 4; np++) {
                uint32_t vb0, vb1, vb2, vb3;
                ldsm4t(sb + 2u * offe(tb + 3, 16 * ks + trow, (2 * np + tck) * 8), vb0, vb1, vb2, vb3);
                mma_bf16(Wa[2*np][0], Wa[2*np][1], Wa[2*np][2], Wa[2*np][3],
                         KA[0], KA[1], KA[2], KA[3], vb0, vb1);
                mma_bf16(Wa[2*np+1][0], Wa[2*np+1][1], Wa[2*np+1][2], Wa[2*np+1][3],
                         KA[0], KA[1], KA[2], KA[3], vb2, vb3);
            }
        }
    }
}

// ---------------- residual + LayerNorm (bf16 attn input) ----------------
__global__ void __launch_bounds__(256) ln_kernel(const float* __restrict__ hin,
                                                 const __nv_bfloat16* __restrict__ attn,
                                                 const float* __restrict__ gamma,
                                                 const float* __restrict__ beta,
                                                 float* __restrict__ out)
{
    int row = blockIdx.x;
    int tid = threadIdx.x;
    const float4* hr = (const float4*)(hin + (size_t)row * DM_);
    float4 hv = hr[tid];
    uint2 ap = ((const uint2*)(attn + (size_t)row * DM_))[tid];
    __nv_bfloat162 a0 = *(__nv_bfloat162*)&ap.x;
    __nv_bfloat162 a1 = *(__nv_bfloat162*)&ap.y;
    float x0 = hv.x + __bfloat162float(a0.x), x1 = hv.y + __bfloat162float(a0.y);
    float x2 = hv.z + __bfloat162float(a1.x), x3 = hv.w + __bfloat162float(a1.y);
    float s  = x0 + x1 + x2 + x3;
    float sq = x0 * x0 + x1 * x1 + x2 * x2 + x3 * x3;
    int lane = tid & 31, w = tid >> 5;
    #pragma unroll
    for (int o = 16; o > 0; o >>= 1) {
        s  += __shfl_xor_sync(0xFFFFFFFFu, s,  o);
        sq += __shfl_xor_sync(0xFFFFFFFFu, sq, o);
    }
    __shared__ float rs[8], rq[8];
    if (lane == 0) { rs[w] = s; rq[w] = sq; }
    __syncthreads();
    float ts = 0.f, tq = 0.f;
    #pragma unroll
    for (int i = 0; i < 8; i++) { ts += rs[i]; tq += rq[i]; }
    float mu  = ts * (1.f / DM_);
    float var = tq * (1.f / DM_) - mu * mu;
    float inv = rsqrtf(var + LN_EPS_);
    const float4 g4 = ((const float4*)gamma)[tid];
    const float4 b4 = ((const float4*)beta)[tid];
    float4 o4;
    o4.x = (x0 - mu) * inv * g4.x + b4.x;
    o4.y = (x1 - mu) * inv * g4.y + b4.y;
    o4.z = (x2 - mu) * inv * g4.z + b4.z;
    o4.w = (x3 - mu) * inv * g4.w + b4.w;
    ((float4*)(out + (size_t)row * DM_))[tid] = o4;
}

// ---------------- launch ----------------
extern "C" void kernel_launch(void* const* d_in, const int* in_sizes, int n_in,
                              void* d_out, int out_size) {
    (void)in_sizes; (void)n_in; (void)out_size;
    const float* h      = (const float*)d_in[0];
    const float* qkv_w  = (const float*)d_in[1];
    const float* o_w    = (const float*)d_in[2];
    const float* gamma  = (const float*)d_in[3];
    const float* beta   = (const float*)d_in[4];
    const float* pi0    = (const float*)d_in[5];
    float* out = (float*)d_out;

    __nv_bfloat16 *hb, *wqkv, *wo, *lo, *attnb;
    cudaGetSymbolAddress((void**)&hb,    g_hb);
    cudaGetSymbolAddress((void**)&wqkv,  g_wqkv);
    cudaGetSymbolAddress((void**)&wo,    g_wo);
    cudaGetSymbolAddress((void**)&lo,    g_lo);
    cudaGetSymbolAddress((void**)&attnb, g_attnb);

    cudaFuncSetAttribute(gemm_nt<0>, cudaFuncAttributeMaxDynamicSharedMemorySize, GEMM_SMEM);
    cudaFuncSetAttribute(gemm_nt<1>, cudaFuncAttributeMaxDynamicSharedMemorySize, GEMM_SMEM);
    cudaFuncSetAttribute(fw_kernel,  cudaFuncAttributeMaxDynamicSharedMemorySize, FW_SMEM);

    cast_kernel<<<(M_*DM_/4 + 255) / 256, 256>>>(h, hb, M_*DM_/4);
    cast_kernel<<<(N1_*DM_/4 + 255) / 256, 256>>>(qkv_w, wqkv, N1_*DM_/4);
    cast_kernel<<<(DM_*HD_/4 + 255) / 256, 256>>>(o_w, wo, DM_*HD_/4);

    // QKV projection with fused phi epilogue -> bf16 q/k1/k2/v
    gemm_nt<0><<<dim3(N1_/128, M_/128), 256, GEMM_SMEM>>>(hb, wqkv, M_, N1_, DM_, nullptr);

    // fused fast-weight + gate
    fw_kernel<<<B_*H_, 256, FW_SMEM>>>(pi0, lo);

    // output projection (bf16 out)
    gemm_nt<1><<<dim3(HD_/128, M_/128), 256, GEMM_SMEM>>>(lo, wo, M_, HD_, HD_, attnb);

    // residual + LN
    ln_kernel<<<M_, 256>>>(h, attnb, gamma, beta, out);
}